// round 4
// baseline (speedup 1.0000x reference)
#include <cuda_runtime.h>
#include <math.h>

#define B 64
#define N 512
#define MLP_H 128
#define N_ACT 512
#define FC_IN 2204            // 512 + 512*3 + 52*3
#define Y_LEN 156
#define NEG_SLOPE 0.2f
#define MAXE 96
#define RSPLIT 4
#define ROWS_PB (N / RSPLIT)  // 128

// -------- scratch (device globals) --------
__device__ __align__(16) float g_sA[B * N * 8];   // per node: s0,A0[3],s1,A1[3]
__device__ float g_g2[B * N * 3];
__device__ int   g_cnt[B * N];
__device__ short g_src[B * N * MAXE];

__device__ __forceinline__ float lrelu(float v) {
    return v >= 0.f ? v : NEG_SLOPE * v;
}
__device__ __forceinline__ float relu(float v) { return v > 0.f ? v : 0.f; }

// ============ init: per-node h1/es/ed, seed self-loop into g_sA / edge list ============
__global__ void k_init(const float* __restrict__ x, const float* __restrict__ W1,
                       const float* __restrict__ a_src1, const float* __restrict__ a_dst1) {
    int n = blockIdx.x * blockDim.x + threadIdx.x;
    if (n >= B * N) return;
    float x0 = x[n * 3 + 0], x1 = x[n * 3 + 1], x2 = x[n * 3 + 2];
    float h[6];
#pragma unroll
    for (int o = 0; o < 6; o++)
        h[o] = x0 * __ldg(&W1[o]) + x1 * __ldg(&W1[6 + o]) + x2 * __ldg(&W1[12 + o]);
    float es0 = h[0] * __ldg(&a_src1[0]) + h[1] * __ldg(&a_src1[1]) + h[2] * __ldg(&a_src1[2]);
    float es1 = h[3] * __ldg(&a_src1[3]) + h[4] * __ldg(&a_src1[4]) + h[5] * __ldg(&a_src1[5]);
    float ed0 = h[0] * __ldg(&a_dst1[0]) + h[1] * __ldg(&a_dst1[1]) + h[2] * __ldg(&a_dst1[2]);
    float ed1 = h[3] * __ldg(&a_dst1[3]) + h[4] * __ldg(&a_dst1[4]) + h[5] * __ldg(&a_dst1[5]);
    float e0 = __expf(lrelu(es0 + ed0));
    float e1 = __expf(lrelu(es1 + ed1));
    float4 p0 = make_float4(e0, e0 * h[0], e0 * h[1], e0 * h[2]);
    float4 p1 = make_float4(e1, e1 * h[3], e1 * h[4], e1 * h[5]);
    *(float4*)&g_sA[n * 8]     = p0;
    *(float4*)&g_sA[n * 8 + 4] = p1;
    g_cnt[n] = 1;
    g_src[(size_t)n * MAXE] = (short)(n & 511);
}

// ============ gat1: adj scan, row-split, atomic accumulation ============
// grid (N/128=4, B, RSPLIT=4), block (32,8). Thread: 4 consecutive cols, 16 row-iters.
__global__ void __launch_bounds__(256) k_gat1(
        const float* __restrict__ adj, const float* __restrict__ x,
        const float* __restrict__ W1, const float* __restrict__ a_src1,
        const float* __restrict__ a_dst1) {
    __shared__ float sh_es[N * 2];
    __shared__ float sh_h[N * 6];
    __shared__ float red[8][128][5];

    const int tx = threadIdx.x, ty = threadIdx.y;
    const int tid = ty * 32 + tx;
    const int b = blockIdx.y;
    const int c0 = blockIdx.x * 128;
    const int row0 = blockIdx.z * ROWS_PB;

    // stage h1/es1 for the whole batch (cheap recompute; 2 nodes/thread)
    for (int n = tid; n < N; n += 256) {
        float x0 = x[(b * N + n) * 3 + 0];
        float x1 = x[(b * N + n) * 3 + 1];
        float x2 = x[(b * N + n) * 3 + 2];
        float h[6];
#pragma unroll
        for (int o = 0; o < 6; o++) {
            h[o] = x0 * __ldg(&W1[o]) + x1 * __ldg(&W1[6 + o]) + x2 * __ldg(&W1[12 + o]);
            sh_h[n * 6 + o] = h[o];
        }
        sh_es[n * 2 + 0] = h[0] * __ldg(&a_src1[0]) + h[1] * __ldg(&a_src1[1]) + h[2] * __ldg(&a_src1[2]);
        sh_es[n * 2 + 1] = h[3] * __ldg(&a_src1[3]) + h[4] * __ldg(&a_src1[4]) + h[5] * __ldg(&a_src1[5]);
    }
    __syncthreads();

    float edv0[4], edv1[4];
#pragma unroll
    for (int k = 0; k < 4; k++) {
        const float* hj = &sh_h[(c0 + 4 * tx + k) * 6];
        edv0[k] = hj[0] * __ldg(&a_dst1[0]) + hj[1] * __ldg(&a_dst1[1]) + hj[2] * __ldg(&a_dst1[2]);
        edv1[k] = hj[3] * __ldg(&a_dst1[3]) + hj[4] * __ldg(&a_dst1[4]) + hj[5] * __ldg(&a_dst1[5]);
    }

    float s0[4] = {0,0,0,0}, s1[4] = {0,0,0,0};
    float A0[4][3] = {}, A1[4][3] = {};

    const float4* adj4 = (const float4*)(adj + (size_t)b * N * N);
    const int c4 = blockIdx.x * 32 + tx;

#pragma unroll 4
    for (int r = 0; r < ROWS_PB / 8; r++) {
        int i = row0 + r * 8 + ty;
        float4 av = adj4[(size_t)i * 128 + c4];
        // fast path: entries are 0.0 or 1.0 -> sum>0 iff any edge
        if (av.x + av.y + av.z + av.w > 0.f) {
            float a[4] = {av.x, av.y, av.z, av.w};
            float esi0 = sh_es[i * 2 + 0];
            float esi1 = sh_es[i * 2 + 1];
            const float* hv = &sh_h[i * 6];
#pragma unroll
            for (int k = 0; k < 4; k++) {
                int j = c0 + 4 * tx + k;
                if (a[k] > 0.f && i != j) {          // self-loop handled in k_init
                    int pos = atomicAdd(&g_cnt[b * N + j], 1);
                    if (pos < MAXE) g_src[(size_t)(b * N + j) * MAXE + pos] = (short)i;
                    float e0 = __expf(lrelu(esi0 + edv0[k]));
                    float e1 = __expf(lrelu(esi1 + edv1[k]));
                    s0[k] += e0; s1[k] += e1;
#pragma unroll
                    for (int d = 0; d < 3; d++) {
                        A0[k][d] += e0 * hv[d];
                        A1[k][d] += e1 * hv[3 + d];
                    }
                }
            }
        }
    }

    // tree-reduce over ty, then atomicAdd partials
#pragma unroll
    for (int pass = 0; pass < 2; pass++) {
#pragma unroll
        for (int k = 0; k < 4; k++) {
            int cl = 4 * tx + k;
            red[ty][cl][0] = pass ? s1[k] : s0[k];
#pragma unroll
            for (int d = 0; d < 3; d++)
                red[ty][cl][1 + d] = pass ? A1[k][d] : A0[k][d];
        }
        __syncthreads();
        for (int dstep = 4; dstep >= 1; dstep >>= 1) {
            if (ty < dstep) {
#pragma unroll
                for (int k = 0; k < 4; k++) {
                    int cl = 4 * tx + k;
#pragma unroll
                    for (int f = 0; f < 4; f++)
                        red[ty][cl][f] += red[ty + dstep][cl][f];
                }
            }
            __syncthreads();
        }
        if (ty == 0) {
#pragma unroll
            for (int k = 0; k < 4; k++) {
                int cl = 4 * tx + k;
                int nj = b * N + c0 + cl;
                if (red[0][cl][0] > 0.f) {
#pragma unroll
                    for (int f = 0; f < 4; f++)
                        atomicAdd(&g_sA[nj * 8 + pass * 4 + f], red[0][cl][f]);
                }
            }
        }
        __syncthreads();
    }
}

// ============ gat2: one warp per target; reconstruct g1 from partials on the fly ============
__global__ void __launch_bounds__(256) k_gat2(
        const float* __restrict__ W2, const float* __restrict__ a_src2,
        const float* __restrict__ a_dst2, const float* __restrict__ b1,
        const float* __restrict__ b2) {
    int gw = (blockIdx.x * 256 + threadIdx.x) >> 5;
    int lane = threadIdx.x & 31;
    if (gw >= B * N) return;
    int b = gw >> 9;

    float w[18];
#pragma unroll
    for (int t = 0; t < 18; t++) w[t] = __ldg(&W2[t]);
    float as0 = __ldg(&a_src2[0]), as1 = __ldg(&a_src2[1]), as2 = __ldg(&a_src2[2]);
    float ad0 = __ldg(&a_dst2[0]), ad1 = __ldg(&a_dst2[1]), ad2 = __ldg(&a_dst2[2]);
    float bb1[6];
#pragma unroll
    for (int t = 0; t < 6; t++) bb1[t] = __ldg(&b1[t]);

    // reconstruct g1 (relu(A/s + b1)) then h2 = g1 @ W2
    auto rec_h = [&](int node, float& h0, float& h1, float& h2) {
        float4 p0 = *(const float4*)&g_sA[(size_t)node * 8];
        float4 p1 = *(const float4*)&g_sA[(size_t)node * 8 + 4];
        float i0 = __frcp_rn(p0.x), i1 = __frcp_rn(p1.x);
        float g[6];
        g[0] = relu(p0.y * i0 + bb1[0]);
        g[1] = relu(p0.z * i0 + bb1[1]);
        g[2] = relu(p0.w * i0 + bb1[2]);
        g[3] = relu(p1.y * i1 + bb1[3]);
        g[4] = relu(p1.z * i1 + bb1[4]);
        g[5] = relu(p1.w * i1 + bb1[5]);
        h0 = h1 = h2 = 0.f;
#pragma unroll
        for (int f = 0; f < 6; f++) {
            h0 += g[f] * w[f * 3 + 0];
            h1 += g[f] * w[f * 3 + 1];
            h2 += g[f] * w[f * 3 + 2];
        }
    };

    float hj0, hj1, hj2;
    rec_h(gw, hj0, hj1, hj2);
    float edj = hj0 * ad0 + hj1 * ad1 + hj2 * ad2;

    int cnt = min(g_cnt[gw], MAXE);
    const short* lst = &g_src[(size_t)gw * MAXE];

    float s = 0.f, a0 = 0.f, a1 = 0.f, a2 = 0.f;
    for (int e = lane; e < cnt; e += 32) {
        int i = lst[e];
        float h0, h1, h2;
        rec_h(b * N + i, h0, h1, h2);
        float es = h0 * as0 + h1 * as1 + h2 * as2;
        float ev = __expf(lrelu(es + edj));
        s += ev; a0 += ev * h0; a1 += ev * h1; a2 += ev * h2;
    }
#pragma unroll
    for (int off = 16; off; off >>= 1) {
        s  += __shfl_xor_sync(0xffffffffu, s, off);
        a0 += __shfl_xor_sync(0xffffffffu, a0, off);
        a1 += __shfl_xor_sync(0xffffffffu, a1, off);
        a2 += __shfl_xor_sync(0xffffffffu, a2, off);
    }
    if (lane == 0) {
        float inv = 1.f / s;
        g_g2[(size_t)gw * 3 + 0] = a0 * inv + __ldg(&b2[0]);
        g_g2[(size_t)gw * 3 + 1] = a1 * inv + __ldg(&b2[1]);
        g_g2[(size_t)gw * 3 + 2] = a2 * inv + __ldg(&b2[2]);
    }
}

// ============ mlp ============
#define BPB 2
#define KSPLIT 16
#define KCHUNK 138
__global__ void __launch_bounds__(512) k_mlp(
        const float* __restrict__ idx, const float* __restrict__ y,
        const float* __restrict__ Wf1, const float* __restrict__ bf1,
        const float* __restrict__ Wf2, const float* __restrict__ bf2,
        float* __restrict__ out) {
    __shared__ float feat[BPB][FC_IN];
    __shared__ float part[KSPLIT][MLP_H][BPB];
    __shared__ float hsh[BPB][MLP_H];

    const int tid = threadIdx.x;
    const int b0 = blockIdx.x * BPB;

#pragma unroll
    for (int bb = 0; bb < BPB; bb++) {
        int b = b0 + bb;
        for (int k = tid; k < FC_IN; k += 512) {
            float v;
            if (k < 512)       v = idx[b * 512 + k];
            else if (k < 2048) v = g_g2[b * 1536 + (k - 512)];
            else               v = y[b * Y_LEN + (k - 2048)];
            feat[bb][k] = v;
        }
    }
    __syncthreads();

    {
        int h4 = (tid & 31) * 4;
        int kp = tid >> 5;
        float acc[BPB][4] = {};
        int k0 = kp * KCHUNK;
        int kend = min(k0 + KCHUNK, FC_IN);
        for (int k = k0; k < kend; k++) {
            float4 w4 = *(const float4*)&Wf1[k * MLP_H + h4];
#pragma unroll
            for (int bb = 0; bb < BPB; bb++) {
                float f = feat[bb][k];
                acc[bb][0] += f * w4.x;
                acc[bb][1] += f * w4.y;
                acc[bb][2] += f * w4.z;
                acc[bb][3] += f * w4.w;
            }
        }
#pragma unroll
        for (int u = 0; u < 4; u++)
#pragma unroll
            for (int bb = 0; bb < BPB; bb++)
                part[kp][h4 + u][bb] = acc[bb][u];
    }
    __syncthreads();
    if (tid < MLP_H) {
#pragma unroll
        for (int bb = 0; bb < BPB; bb++) {
            float h = __ldg(&bf1[tid]);
#pragma unroll
            for (int kp = 0; kp < KSPLIT; kp++) h += part[kp][tid][bb];
            hsh[bb][tid] = h > 0.f ? h : 0.f;
        }
    }
    __syncthreads();

    {
        int o = tid;
        float acc[BPB];
#pragma unroll
        for (int bb = 0; bb < BPB; bb++) acc[bb] = __ldg(&bf2[o]);
#pragma unroll 4
        for (int t2 = 0; t2 < MLP_H; t2++) {
            float w = Wf2[t2 * N_ACT + o];
#pragma unroll
            for (int bb = 0; bb < BPB; bb++) acc[bb] += hsh[bb][t2] * w;
        }
#pragma unroll
        for (int bb = 0; bb < BPB; bb++) out[(b0 + bb) * N_ACT + o] = acc[bb];
    }
}

extern "C" void kernel_launch(void* const* d_in, const int* in_sizes, int n_in,
                              void* d_out, int out_size) {
    const float* idx    = (const float*)d_in[0];
    const float* x      = (const float*)d_in[1];
    const float* y      = (const float*)d_in[2];
    const float* adj    = (const float*)d_in[3];
    const float* W1     = (const float*)d_in[4];
    const float* a_src1 = (const float*)d_in[5];
    const float* a_dst1 = (const float*)d_in[6];
    const float* b1     = (const float*)d_in[7];
    const float* W2     = (const float*)d_in[8];
    const float* a_src2 = (const float*)d_in[9];
    const float* a_dst2 = (const float*)d_in[10];
    const float* b2     = (const float*)d_in[11];
    const float* Wf1    = (const float*)d_in[12];
    const float* bf1    = (const float*)d_in[13];
    const float* Wf2    = (const float*)d_in[14];
    const float* bf2    = (const float*)d_in[15];
    float* out = (float*)d_out;

    k_init<<<(B * N + 255) / 256, 256>>>(x, W1, a_src1, a_dst1);
    k_gat1<<<dim3(N / 128, B, RSPLIT), dim3(32, 8)>>>(adj, x, W1, a_src1, a_dst1);
    k_gat2<<<(B * N * 32 + 255) / 256, 256>>>(W2, a_src2, a_dst2, b1, b2);
    k_mlp<<<B / BPB, 512>>>(idx, y, Wf1, bf1, Wf2, bf2, out);
}

// round 6
// speedup vs baseline: 1.1031x; 1.1031x over previous
#include <cuda_runtime.h>
#include <math.h>

#define B 64
#define N 512
#define MLP_H 128
#define N_ACT 512
#define FC_IN 2204            // 512 + 512*3 + 52*3
#define Y_LEN 156
#define NEG_SLOPE 0.2f
#define MAXE 96
#define RSPLIT 8
#define ROWS_PB (N / RSPLIT)  // 64

#define KTILE 128
#define KTILES 18             // ceil(2204/128)
#define HTILE 32

// -------- scratch (device globals) --------
__device__ __align__(16) float g_sA[B * N * 8];   // per node: s0,A0[3],s1,A1[3]
__device__ float g_g2[B * N * 3];
__device__ float g_hid[B * MLP_H];                // layer-1 pre-activation accumulators
__device__ int   g_cnt[B * N];
__device__ short g_src[B * N * MAXE];

__device__ __forceinline__ float lrelu(float v) {
    return v >= 0.f ? v : NEG_SLOPE * v;
}
__device__ __forceinline__ float relu(float v) { return v > 0.f ? v : 0.f; }

// ============ init: per-node h1/es/ed, seed self-loop; zero g_hid ============
__global__ void k_init(const float* __restrict__ x, const float* __restrict__ W1,
                       const float* __restrict__ a_src1, const float* __restrict__ a_dst1) {
    int n = blockIdx.x * blockDim.x + threadIdx.x;
    if (n >= B * N) return;
    if (n < B * MLP_H) g_hid[n] = 0.f;
    float x0 = x[n * 3 + 0], x1 = x[n * 3 + 1], x2 = x[n * 3 + 2];
    float h[6];
#pragma unroll
    for (int o = 0; o < 6; o++)
        h[o] = x0 * __ldg(&W1[o]) + x1 * __ldg(&W1[6 + o]) + x2 * __ldg(&W1[12 + o]);
    float es0 = h[0] * __ldg(&a_src1[0]) + h[1] * __ldg(&a_src1[1]) + h[2] * __ldg(&a_src1[2]);
    float es1 = h[3] * __ldg(&a_src1[3]) + h[4] * __ldg(&a_src1[4]) + h[5] * __ldg(&a_src1[5]);
    float ed0 = h[0] * __ldg(&a_dst1[0]) + h[1] * __ldg(&a_dst1[1]) + h[2] * __ldg(&a_dst1[2]);
    float ed1 = h[3] * __ldg(&a_dst1[3]) + h[4] * __ldg(&a_dst1[4]) + h[5] * __ldg(&a_dst1[5]);
    float e0 = __expf(lrelu(es0 + ed0));
    float e1 = __expf(lrelu(es1 + ed1));
    *(float4*)&g_sA[n * 8]     = make_float4(e0, e0 * h[0], e0 * h[1], e0 * h[2]);
    *(float4*)&g_sA[n * 8 + 4] = make_float4(e1, e1 * h[3], e1 * h[4], e1 * h[5]);
    g_cnt[n] = 1;
    g_src[(size_t)n * MAXE] = (short)(n & 511);
}

// ============ gat1: adj scan, row-split, atomic accumulation ============
// grid (N/128=4, B, RSPLIT=8), block (32,8).
__global__ void __launch_bounds__(256) k_gat1(
        const float* __restrict__ adj, const float* __restrict__ x,
        const float* __restrict__ W1, const float* __restrict__ a_src1,
        const float* __restrict__ a_dst1) {
    __shared__ float sh_es[N * 2];
    __shared__ float sh_h[N * 6];
    __shared__ float red[8][128][5];

    const int tx = threadIdx.x, ty = threadIdx.y;
    const int tid = ty * 32 + tx;
    const int b = blockIdx.y;
    const int c0 = blockIdx.x * 128;
    const int row0 = blockIdx.z * ROWS_PB;

    for (int n = tid; n < N; n += 256) {
        float x0 = x[(b * N + n) * 3 + 0];
        float x1 = x[(b * N + n) * 3 + 1];
        float x2 = x[(b * N + n) * 3 + 2];
        float h[6];
#pragma unroll
        for (int o = 0; o < 6; o++) {
            h[o] = x0 * __ldg(&W1[o]) + x1 * __ldg(&W1[6 + o]) + x2 * __ldg(&W1[12 + o]);
            sh_h[n * 6 + o] = h[o];
        }
        sh_es[n * 2 + 0] = h[0] * __ldg(&a_src1[0]) + h[1] * __ldg(&a_src1[1]) + h[2] * __ldg(&a_src1[2]);
        sh_es[n * 2 + 1] = h[3] * __ldg(&a_src1[3]) + h[4] * __ldg(&a_src1[4]) + h[5] * __ldg(&a_src1[5]);
    }
    __syncthreads();

    float edv0[4], edv1[4];
#pragma unroll
    for (int k = 0; k < 4; k++) {
        const float* hj = &sh_h[(c0 + 4 * tx + k) * 6];
        edv0[k] = hj[0] * __ldg(&a_dst1[0]) + hj[1] * __ldg(&a_dst1[1]) + hj[2] * __ldg(&a_dst1[2]);
        edv1[k] = hj[3] * __ldg(&a_dst1[3]) + hj[4] * __ldg(&a_dst1[4]) + hj[5] * __ldg(&a_dst1[5]);
    }

    float s0[4] = {0,0,0,0}, s1[4] = {0,0,0,0};
    float A0[4][3] = {}, A1[4][3] = {};

    const float4* adj4 = (const float4*)(adj + (size_t)b * N * N);
    const int c4 = blockIdx.x * 32 + tx;

#pragma unroll
    for (int r = 0; r < ROWS_PB / 8; r++) {
        int i = row0 + r * 8 + ty;
        float4 av = adj4[(size_t)i * 128 + c4];
        if (av.x + av.y + av.z + av.w > 0.f) {     // entries are 0/1
            float a[4] = {av.x, av.y, av.z, av.w};
            float esi0 = sh_es[i * 2 + 0];
            float esi1 = sh_es[i * 2 + 1];
            const float* hv = &sh_h[i * 6];
#pragma unroll
            for (int k = 0; k < 4; k++) {
                int j = c0 + 4 * tx + k;
                if (a[k] > 0.f && i != j) {
                    int pos = atomicAdd(&g_cnt[b * N + j], 1);
                    if (pos < MAXE) g_src[(size_t)(b * N + j) * MAXE + pos] = (short)i;
                    float e0 = __expf(lrelu(esi0 + edv0[k]));
                    float e1 = __expf(lrelu(esi1 + edv1[k]));
                    s0[k] += e0; s1[k] += e1;
#pragma unroll
                    for (int d = 0; d < 3; d++) {
                        A0[k][d] += e0 * hv[d];
                        A1[k][d] += e1 * hv[3 + d];
                    }
                }
            }
        }
    }

#pragma unroll
    for (int pass = 0; pass < 2; pass++) {
#pragma unroll
        for (int k = 0; k < 4; k++) {
            int cl = 4 * tx + k;
            red[ty][cl][0] = pass ? s1[k] : s0[k];
#pragma unroll
            for (int d = 0; d < 3; d++)
                red[ty][cl][1 + d] = pass ? A1[k][d] : A0[k][d];
        }
        __syncthreads();
        for (int dstep = 4; dstep >= 1; dstep >>= 1) {
            if (ty < dstep) {
#pragma unroll
                for (int k = 0; k < 4; k++) {
                    int cl = 4 * tx + k;
#pragma unroll
                    for (int f = 0; f < 4; f++)
                        red[ty][cl][f] += red[ty + dstep][cl][f];
                }
            }
            __syncthreads();
        }
        if (ty == 0) {
#pragma unroll
            for (int k = 0; k < 4; k++) {
                int cl = 4 * tx + k;
                int nj = b * N + c0 + cl;
                if (red[0][cl][0] > 0.f) {
#pragma unroll
                    for (int f = 0; f < 4; f++)
                        atomicAdd(&g_sA[nj * 8 + pass * 4 + f], red[0][cl][f]);
                }
            }
        }
        __syncthreads();
    }
}

// ============ gat2: one warp per target; reconstruct g1 from partials on the fly ============
__global__ void __launch_bounds__(256) k_gat2(
        const float* __restrict__ W2, const float* __restrict__ a_src2,
        const float* __restrict__ a_dst2, const float* __restrict__ b1,
        const float* __restrict__ b2) {
    int gw = (blockIdx.x * 256 + threadIdx.x) >> 5;
    int lane = threadIdx.x & 31;
    if (gw >= B * N) return;
    int b = gw >> 9;

    float w[18];
#pragma unroll
    for (int t = 0; t < 18; t++) w[t] = __ldg(&W2[t]);
    float as0 = __ldg(&a_src2[0]), as1 = __ldg(&a_src2[1]), as2 = __ldg(&a_src2[2]);
    float ad0 = __ldg(&a_dst2[0]), ad1 = __ldg(&a_dst2[1]), ad2 = __ldg(&a_dst2[2]);
    float bb1[6];
#pragma unroll
    for (int t = 0; t < 6; t++) bb1[t] = __ldg(&b1[t]);

    auto rec_h = [&](int node, float& h0, float& h1, float& h2) {
        float4 p0 = *(const float4*)&g_sA[(size_t)node * 8];
        float4 p1 = *(const float4*)&g_sA[(size_t)node * 8 + 4];
        float i0 = __frcp_rn(p0.x), i1 = __frcp_rn(p1.x);
        float g[6];
        g[0] = relu(p0.y * i0 + bb1[0]);
        g[1] = relu(p0.z * i0 + bb1[1]);
        g[2] = relu(p0.w * i0 + bb1[2]);
        g[3] = relu(p1.y * i1 + bb1[3]);
        g[4] = relu(p1.z * i1 + bb1[4]);
        g[5] = relu(p1.w * i1 + bb1[5]);
        h0 = h1 = h2 = 0.f;
#pragma unroll
        for (int f = 0; f < 6; f++) {
            h0 += g[f] * w[f * 3 + 0];
            h1 += g[f] * w[f * 3 + 1];
            h2 += g[f] * w[f * 3 + 2];
        }
    };

    float hj0, hj1, hj2;
    rec_h(gw, hj0, hj1, hj2);
    float edj = hj0 * ad0 + hj1 * ad1 + hj2 * ad2;

    int cnt = min(g_cnt[gw], MAXE);
    const short* lst = &g_src[(size_t)gw * MAXE];

    float s = 0.f, a0 = 0.f, a1 = 0.f, a2 = 0.f;
    for (int e = lane; e < cnt; e += 32) {
        int i = lst[e];
        float h0, h1, h2;
        rec_h(b * N + i, h0, h1, h2);
        float es = h0 * as0 + h1 * as1 + h2 * as2;
        float ev = __expf(lrelu(es + edj));
        s += ev; a0 += ev * h0; a1 += ev * h1; a2 += ev * h2;
    }
#pragma unroll
    for (int off = 16; off; off >>= 1) {
        s  += __shfl_xor_sync(0xffffffffu, s, off);
        a0 += __shfl_xor_sync(0xffffffffu, a0, off);
        a1 += __shfl_xor_sync(0xffffffffu, a1, off);
        a2 += __shfl_xor_sync(0xffffffffu, a2, off);
    }
    if (lane == 0) {
        float inv = 1.f / s;
        g_g2[(size_t)gw * 3 + 0] = a0 * inv + __ldg(&b2[0]);
        g_g2[(size_t)gw * 3 + 1] = a1 * inv + __ldg(&b2[1]);
        g_g2[(size_t)gw * 3 + 2] = a2 * inv + __ldg(&b2[2]);
    }
}

// ============ mlp1: layer-1 GEMM over all batches, weights loaded once ============
// grid (MLP_H/HTILE=4, KTILES=18), block 256. Accumulates into g_hid via atomics.
// SMEM: Wsh 16KB + fsh 32KB = 49152 B = 0xC000 (exactly at the static limit).
__global__ void __launch_bounds__(256) k_mlp1(
        const float* __restrict__ idx, const float* __restrict__ y,
        const float* __restrict__ Wf1) {
    __shared__ float Wsh[KTILE * HTILE];          // [k][hid], 16 KB
    __shared__ float fsh[KTILE * B];              // [k][b], 32 KB, no pad needed

    const int tid = threadIdx.x;
    const int hid0 = blockIdx.x * HTILE;
    const int k0 = blockIdx.y * KTILE;

    // load W tile (zero-pad past FC_IN); lanes vary h -> coalesced
#pragma unroll
    for (int i = 0; i < (KTILE * HTILE) / 256; i++) {
        int e = tid + i * 256;
        int k = e >> 5, h = e & 31;
        int kk = k0 + k;
        Wsh[e] = (kk < FC_IN) ? Wf1[kk * MLP_H + hid0 + h] : 0.f;
    }
    // gather feat tile for all 64 batches; [k][b] layout: lanes vary b -> conflict-free STS
#pragma unroll
    for (int i = 0; i < (B * KTILE) / 256; i++) {
        int e = tid + i * 256;
        int b = e & 63, k = e >> 6;
        int kk = k0 + k;
        float v = 0.f;
        if (kk < 512)            v = idx[b * 512 + kk];
        else if (kk < 2048)      v = g_g2[b * 1536 + (kk - 512)];
        else if (kk < FC_IN)     v = y[b * Y_LEN + (kk - 2048)];
        fsh[k * B + b] = v;
    }
    __syncthreads();

    // thread: batch b = tid&63 (lane-consecutive), hid block of 8 = (tid>>6)*8
    const int b = tid & 63;
    const int h8 = (tid >> 6) * 8;
    float acc[8] = {};
#pragma unroll 4
    for (int k = 0; k < KTILE; k++) {
        float f = fsh[k * B + b];                         // conflict-free
        float4 w0 = *(const float4*)&Wsh[k * HTILE + h8]; // warp-uniform broadcast
        float4 w1 = *(const float4*)&Wsh[k * HTILE + h8 + 4];
        acc[0] += f * w0.x; acc[1] += f * w0.y; acc[2] += f * w0.z; acc[3] += f * w0.w;
        acc[4] += f * w1.x; acc[5] += f * w1.y; acc[6] += f * w1.z; acc[7] += f * w1.w;
    }
#pragma unroll
    for (int u = 0; u < 8; u++)
        atomicAdd(&g_hid[b * MLP_H + hid0 + h8 + u], acc[u]);
}

// ============ mlp2: relu(hid+bf1) @ Wf2 + bf2; one thread per output element ============
__global__ void __launch_bounds__(256) k_mlp2(
        const float* __restrict__ bf1, const float* __restrict__ Wf2,
        const float* __restrict__ bf2, float* __restrict__ out) {
    int gid = blockIdx.x * 256 + threadIdx.x;      // 32768 threads
    int b = gid >> 9;
    int o = gid & 511;
    const float* hrow = &g_hid[b * MLP_H];
    float acc = __ldg(&bf2[o]);
#pragma unroll 8
    for (int t = 0; t < MLP_H; t++) {
        float h = relu(hrow[t] + __ldg(&bf1[t]));  // broadcast across warp
        acc += h * Wf2[t * N_ACT + o];             // coalesced
    }
    out[gid] = acc;
}

extern "C" void kernel_launch(void* const* d_in, const int* in_sizes, int n_in,
                              void* d_out, int out_size) {
    const float* idx    = (const float*)d_in[0];
    const float* x      = (const float*)d_in[1];
    const float* y      = (const float*)d_in[2];
    const float* adj    = (const float*)d_in[3];
    const float* W1     = (const float*)d_in[4];
    const float* a_src1 = (const float*)d_in[5];
    const float* a_dst1 = (const float*)d_in[6];
    const float* b1     = (const float*)d_in[7];
    const float* W2     = (const float*)d_in[8];
    const float* a_src2 = (const float*)d_in[9];
    const float* a_dst2 = (const float*)d_in[10];
    const float* b2     = (const float*)d_in[11];
    const float* Wf1    = (const float*)d_in[12];
    const float* bf1    = (const float*)d_in[13];
    const float* Wf2    = (const float*)d_in[14];
    const float* bf2    = (const float*)d_in[15];
    float* out = (float*)d_out;

    k_init<<<(B * N + 255) / 256, 256>>>(x, W1, a_src1, a_dst1);
    k_gat1<<<dim3(N / 128, B, RSPLIT), dim3(32, 8)>>>(adj, x, W1, a_src1, a_dst1);
    k_gat2<<<(B * N * 32 + 255) / 256, 256>>>(W2, a_src2, a_dst2, b1, b2);
    k_mlp1<<<dim3(MLP_H / HTILE, KTILES), 256>>>(idx, y, Wf1);
    k_mlp2<<<(B * N_ACT) / 256, 256>>>(bf1, Wf2, bf2, out);
}

// round 7
// speedup vs baseline: 2.2597x; 2.0484x over previous
#include <cuda_runtime.h>
#include <math.h>

#define B 64
#define N 512
#define BN (B * N)
#define MLP_H 128
#define N_ACT 512
#define FC_IN 2204            // 512 + 512*3 + 52*3
#define Y_LEN 156
#define NEG_SLOPE 0.2f
#define MAXE 96

// -------- scratch (device globals) --------
__device__ __align__(16) float g_hes[BN * 8];  // per node: es0,es1,h0,h1 | h2,h3,h4,h5
__device__ __align__(8)  float g_ed[BN * 2];   // per node: ed0,ed1
__device__ __align__(16) float g_g1[BN * 8];   // per node: g1[6], pad[2]
__device__ float g_g2[BN * 3];
__device__ float g_hid[B * MLP_H];
__device__ int   g_cnt[BN];
__device__ short g_src[BN * MAXE];

__device__ __forceinline__ float lrelu(float v) { return v >= 0.f ? v : NEG_SLOPE * v; }
__device__ __forceinline__ float relu(float v)  { return v > 0.f ? v : 0.f; }

// ============ init: h1/es/ed per node; seed self-loop; zero g_hid ============
__global__ void k_init(const float* __restrict__ x, const float* __restrict__ W1,
                       const float* __restrict__ a_src1, const float* __restrict__ a_dst1) {
    int n = blockIdx.x * 256 + threadIdx.x;
    if (n >= BN) return;
    if (n < B * MLP_H) g_hid[n] = 0.f;
    float x0 = x[n * 3 + 0], x1 = x[n * 3 + 1], x2 = x[n * 3 + 2];
    float h[6];
#pragma unroll
    for (int o = 0; o < 6; o++)
        h[o] = x0 * __ldg(&W1[o]) + x1 * __ldg(&W1[6 + o]) + x2 * __ldg(&W1[12 + o]);
    float es0 = h[0] * __ldg(&a_src1[0]) + h[1] * __ldg(&a_src1[1]) + h[2] * __ldg(&a_src1[2]);
    float es1 = h[3] * __ldg(&a_src1[3]) + h[4] * __ldg(&a_src1[4]) + h[5] * __ldg(&a_src1[5]);
    float ed0 = h[0] * __ldg(&a_dst1[0]) + h[1] * __ldg(&a_dst1[1]) + h[2] * __ldg(&a_dst1[2]);
    float ed1 = h[3] * __ldg(&a_dst1[3]) + h[4] * __ldg(&a_dst1[4]) + h[5] * __ldg(&a_dst1[5]);
    *(float4*)&g_hes[n * 8]     = make_float4(es0, es1, h[0], h[1]);
    *(float4*)&g_hes[n * 8 + 4] = make_float4(h[2], h[3], h[4], h[5]);
    g_ed[n * 2 + 0] = ed0;
    g_ed[n * 2 + 1] = ed1;
    g_cnt[n] = 1;
    g_src[(size_t)n * MAXE] = (short)(n & 511);
}

// ============ scan: adj -> edge lists, pure bandwidth ============
// grid (32, B): block handles 16 rows of one batch; 256 threads; 8 iters x (2 rows x 128 float4)
__global__ void __launch_bounds__(256) k_scan(const float* __restrict__ adj) {
    const int b = blockIdx.y;
    const int row0 = blockIdx.x * 16;
    const float4* a4 = (const float4*)(adj + (size_t)b * N * N);
    const int tid = threadIdx.x;
    const int col4 = tid & 127;
    const int rhalf = tid >> 7;
    const int jb = col4 * 4;
#pragma unroll
    for (int it = 0; it < 8; it++) {
        int i = row0 + it * 2 + rhalf;
        float4 av = a4[(size_t)i * 128 + col4];
        if (av.x + av.y + av.z + av.w > 0.f) {   // entries are 0/1
            if (av.x > 0.f && i != jb) {
                int p = atomicAdd(&g_cnt[b * N + jb], 1);
                if (p < MAXE) g_src[(size_t)(b * N + jb) * MAXE + p] = (short)i;
            }
            if (av.y > 0.f && i != jb + 1) {
                int p = atomicAdd(&g_cnt[b * N + jb + 1], 1);
                if (p < MAXE) g_src[(size_t)(b * N + jb + 1) * MAXE + p] = (short)i;
            }
            if (av.z > 0.f && i != jb + 2) {
                int p = atomicAdd(&g_cnt[b * N + jb + 2], 1);
                if (p < MAXE) g_src[(size_t)(b * N + jb + 2) * MAXE + p] = (short)i;
            }
            if (av.w > 0.f && i != jb + 3) {
                int p = atomicAdd(&g_cnt[b * N + jb + 3], 1);
                if (p < MAXE) g_src[(size_t)(b * N + jb + 3) * MAXE + p] = (short)i;
            }
        }
    }
}

// ============ agg1: layer-1 aggregation, 8 lanes per target ============
__global__ void __launch_bounds__(256) k_agg1(const float* __restrict__ b1) {
    int gid = blockIdx.x * 256 + threadIdx.x;     // BN*8 threads
    int t = gid >> 3;
    int sl = gid & 7;
    int b = t >> 9;
    float ed0 = g_ed[t * 2 + 0], ed1 = g_ed[t * 2 + 1];
    int cnt = min(g_cnt[t], MAXE);
    const short* lst = &g_src[(size_t)t * MAXE];

    float s0 = 0.f, s1 = 0.f;
    float A00 = 0.f, A01 = 0.f, A02 = 0.f, A10 = 0.f, A11 = 0.f, A12 = 0.f;
    for (int e = sl; e < cnt; e += 8) {
        int i = lst[e];
        float4 p0 = *(const float4*)&g_hes[(size_t)(b * N + i) * 8];
        float4 p1 = *(const float4*)&g_hes[(size_t)(b * N + i) * 8 + 4];
        float e0 = __expf(lrelu(p0.x + ed0));
        float e1 = __expf(lrelu(p0.y + ed1));
        s0 += e0; A00 += e0 * p0.z; A01 += e0 * p0.w; A02 += e0 * p1.x;
        s1 += e1; A10 += e1 * p1.y; A11 += e1 * p1.z; A12 += e1 * p1.w;
    }
#pragma unroll
    for (int off = 4; off; off >>= 1) {
        s0  += __shfl_xor_sync(0xffffffffu, s0, off);
        s1  += __shfl_xor_sync(0xffffffffu, s1, off);
        A00 += __shfl_xor_sync(0xffffffffu, A00, off);
        A01 += __shfl_xor_sync(0xffffffffu, A01, off);
        A02 += __shfl_xor_sync(0xffffffffu, A02, off);
        A10 += __shfl_xor_sync(0xffffffffu, A10, off);
        A11 += __shfl_xor_sync(0xffffffffu, A11, off);
        A12 += __shfl_xor_sync(0xffffffffu, A12, off);
    }
    if (sl == 0) {
        float i0 = 1.f / s0, i1 = 1.f / s1;
        float4 o0 = make_float4(relu(A00 * i0 + __ldg(&b1[0])),
                                relu(A01 * i0 + __ldg(&b1[1])),
                                relu(A02 * i0 + __ldg(&b1[2])),
                                relu(A10 * i1 + __ldg(&b1[3])));
        float4 o1 = make_float4(relu(A11 * i1 + __ldg(&b1[4])),
                                relu(A12 * i1 + __ldg(&b1[5])), 0.f, 0.f);
        *(float4*)&g_g1[(size_t)t * 8]     = o0;
        *(float4*)&g_g1[(size_t)t * 8 + 4] = o1;
    }
}

// ============ agg2: layer-2 aggregation, 8 lanes per target, h2 recomputed per edge ============
__global__ void __launch_bounds__(256) k_agg2(
        const float* __restrict__ W2, const float* __restrict__ a_src2,
        const float* __restrict__ a_dst2, const float* __restrict__ b2) {
    int gid = blockIdx.x * 256 + threadIdx.x;     // BN*8 threads
    int t = gid >> 3;
    int sl = gid & 7;
    int b = t >> 9;

    float w[18];
#pragma unroll
    for (int q = 0; q < 18; q++) w[q] = __ldg(&W2[q]);
    float as0 = __ldg(&a_src2[0]), as1 = __ldg(&a_src2[1]), as2 = __ldg(&a_src2[2]);
    float ad0 = __ldg(&a_dst2[0]), ad1 = __ldg(&a_dst2[1]), ad2 = __ldg(&a_dst2[2]);

    auto rec_h = [&](int node, float& h0, float& h1, float& h2) {
        float4 q0 = *(const float4*)&g_g1[(size_t)node * 8];
        float4 q1 = *(const float4*)&g_g1[(size_t)node * 8 + 4];
        float g[6] = {q0.x, q0.y, q0.z, q0.w, q1.x, q1.y};
        h0 = h1 = h2 = 0.f;
#pragma unroll
        for (int f = 0; f < 6; f++) {
            h0 += g[f] * w[f * 3 + 0];
            h1 += g[f] * w[f * 3 + 1];
            h2 += g[f] * w[f * 3 + 2];
        }
    };

    float hj0, hj1, hj2;
    rec_h(t, hj0, hj1, hj2);
    float edj = hj0 * ad0 + hj1 * ad1 + hj2 * ad2;

    int cnt = min(g_cnt[t], MAXE);
    const short* lst = &g_src[(size_t)t * MAXE];

    float s = 0.f, a0 = 0.f, a1 = 0.f, a2 = 0.f;
    for (int e = sl; e < cnt; e += 8) {
        int i = lst[e];
        float h0, h1, h2;
        rec_h(b * N + i, h0, h1, h2);
        float es = h0 * as0 + h1 * as1 + h2 * as2;
        float ev = __expf(lrelu(es + edj));
        s += ev; a0 += ev * h0; a1 += ev * h1; a2 += ev * h2;
    }
#pragma unroll
    for (int off = 4; off; off >>= 1) {
        s  += __shfl_xor_sync(0xffffffffu, s, off);
        a0 += __shfl_xor_sync(0xffffffffu, a0, off);
        a1 += __shfl_xor_sync(0xffffffffu, a1, off);
        a2 += __shfl_xor_sync(0xffffffffu, a2, off);
    }
    if (sl == 0) {
        float inv = 1.f / s;
        g_g2[(size_t)t * 3 + 0] = a0 * inv + __ldg(&b2[0]);
        g_g2[(size_t)t * 3 + 1] = a1 * inv + __ldg(&b2[1]);
        g_g2[(size_t)t * 3 + 2] = a2 * inv + __ldg(&b2[2]);
    }
}

// ============ mlp1: layer-1 GEMM; grid (4 hid x 18 k x 2 batch) = 144 blocks ============
#define KTILE 128
#define KTILES 18
#define HTILE 32
#define BTILE 32
__global__ void __launch_bounds__(256) k_mlp1(
        const float* __restrict__ idx, const float* __restrict__ y,
        const float* __restrict__ Wf1) {
    __shared__ float Wsh[KTILE * HTILE];      // [k][h], 16 KB
    __shared__ float fsh[BTILE * (KTILE + 1)];// [b][k] pad, 16.5 KB

    const int tid = threadIdx.x;
    const int hid0 = blockIdx.x * HTILE;
    const int k0 = blockIdx.y * KTILE;
    const int b0 = blockIdx.z * BTILE;

    // Wsh: lanes vary h -> coalesced; zero-pad past FC_IN
#pragma unroll
    for (int i = 0; i < (KTILE * HTILE) / 256; i++) {
        int e = tid + i * 256;
        int k = e >> 5, h = e & 31;
        int kk = k0 + k;
        Wsh[e] = (kk < FC_IN) ? Wf1[kk * MLP_H + hid0 + h] : 0.f;
    }
    // fsh gather: lanes vary k -> coalesced global reads, consecutive SMEM writes
#pragma unroll
    for (int i = 0; i < (BTILE * KTILE) / 256; i++) {
        int e = tid + i * 256;
        int bb = e >> 7, k = e & 127;
        int kk = k0 + k;
        int b = b0 + bb;
        float v = 0.f;
        if (kk < 512)            v = idx[b * 512 + kk];
        else if (kk < 2048)      v = g_g2[b * 1536 + (kk - 512)];
        else if (kk < FC_IN)     v = y[b * Y_LEN + (kk - 2048)];
        fsh[bb * (KTILE + 1) + k] = v;
    }
    __syncthreads();

    const int bb = tid & 31;             // lanes vary b: fsh stride 129 -> conflict-free
    const int h4 = (tid >> 5) * 4;       // warp-uniform
    float acc[4] = {};
#pragma unroll 4
    for (int k = 0; k < KTILE; k++) {
        float f = fsh[bb * (KTILE + 1) + k];
        float4 w = *(const float4*)&Wsh[k * HTILE + h4];
        acc[0] += f * w.x; acc[1] += f * w.y; acc[2] += f * w.z; acc[3] += f * w.w;
    }
#pragma unroll
    for (int u = 0; u < 4; u++)
        atomicAdd(&g_hid[(b0 + bb) * MLP_H + hid0 + h4 + u], acc[u]);
}

// ============ mlp2: out = relu(hid+bf1) @ Wf2 + bf2 ============
__global__ void __launch_bounds__(256) k_mlp2(
        const float* __restrict__ bf1, const float* __restrict__ Wf2,
        const float* __restrict__ bf2, float* __restrict__ out) {
    __shared__ float sh[MLP_H];
    const int b = blockIdx.x >> 1;
    const int o = (blockIdx.x & 1) * 256 + threadIdx.x;
    if (threadIdx.x < MLP_H)
        sh[threadIdx.x] = relu(g_hid[b * MLP_H + threadIdx.x] + __ldg(&bf1[threadIdx.x]));
    __syncthreads();
    float acc = __ldg(&bf2[o]);
#pragma unroll 8
    for (int t = 0; t < MLP_H; t++)
        acc += sh[t] * Wf2[t * N_ACT + o];
    out[b * N_ACT + o] = acc;
}

extern "C" void kernel_launch(void* const* d_in, const int* in_sizes, int n_in,
                              void* d_out, int out_size) {
    const float* idx    = (const float*)d_in[0];
    const float* x      = (const float*)d_in[1];
    const float* y      = (const float*)d_in[2];
    const float* adj    = (const float*)d_in[3];
    const float* W1     = (const float*)d_in[4];
    const float* a_src1 = (const float*)d_in[5];
    const float* a_dst1 = (const float*)d_in[6];
    const float* b1     = (const float*)d_in[7];
    const float* W2     = (const float*)d_in[8];
    const float* a_src2 = (const float*)d_in[9];
    const float* a_dst2 = (const float*)d_in[10];
    const float* b2     = (const float*)d_in[11];
    const float* Wf1    = (const float*)d_in[12];
    const float* bf1    = (const float*)d_in[13];
    const float* Wf2    = (const float*)d_in[14];
    const float* bf2    = (const float*)d_in[15];
    float* out = (float*)d_out;

    k_init<<<BN / 256, 256>>>(x, W1, a_src1, a_dst1);
    k_scan<<<dim3(32, B), 256>>>(adj);
    k_agg1<<<BN * 8 / 256, 256>>>(b1);
    k_agg2<<<BN * 8 / 256, 256>>>(W2, a_src2, a_dst2, b2);
    k_mlp1<<<dim3(MLP_H / HTILE, KTILES, B / BTILE), 256>>>(idx, y, Wf1);
    k_mlp2<<<B * 2, 256>>>(bf1, Wf2, bf2, out);
}

// round 8
// speedup vs baseline: 2.3760x; 1.0515x over previous
#include <cuda_runtime.h>
#include <math.h>

#define B 64
#define N 512
#define BN (B * N)
#define MLP_H 128
#define N_ACT 512
#define FC_IN 2204            // 512 + 512*3 + 52*3
#define Y_LEN 156
#define NEG_SLOPE 0.2f
#define MAXE 96

// -------- scratch (device globals; zero-initialized at module load) --------
__device__ __align__(16) float g_hes[BN * 8];   // per node: es0,es1,h0,h1 | h2,h3,h4,h5
__device__ __align__(8)  float g_ed[BN * 2];    // per node: ed0,ed1
__device__ __align__(16) float g_h2es[BN * 4];  // per node: es2,h2_0,h2_1,h2_2
__device__ float g_ed2[BN];
__device__ float g_g2[BN * 3];
__device__ float g_hid[B * MLP_H];
__device__ int   g_cnt[BN];                     // zeroed by k_mlp2 tail each call
__device__ short g_src[BN * MAXE];

__device__ __forceinline__ float lrelu(float v) { return v >= 0.f ? v : NEG_SLOPE * v; }
__device__ __forceinline__ float relu(float v)  { return v > 0.f ? v : 0.f; }

// ============ scan (+fused init): adj -> edge lists; per-node h/es/ed; zero g_hid ============
// grid (32, B), 256 threads. Block scans 16 rows of one batch AND initializes 16 nodes.
__global__ void __launch_bounds__(256) k_scan(
        const float* __restrict__ adj, const float* __restrict__ x,
        const float* __restrict__ W1, const float* __restrict__ a_src1,
        const float* __restrict__ a_dst1) {
    const int tid = threadIdx.x;
    const int b = blockIdx.y;
    const int blk = b * 32 + blockIdx.x;           // 0..2047

    // -- fused init: 16 nodes per block (scan does not read these arrays; no sync needed) --
    if (tid < 16) {
        int n = blk * 16 + tid;                    // global node id, covers [0, BN)
        float x0 = x[n * 3 + 0], x1 = x[n * 3 + 1], x2 = x[n * 3 + 2];
        float h[6];
#pragma unroll
        for (int o = 0; o < 6; o++)
            h[o] = x0 * __ldg(&W1[o]) + x1 * __ldg(&W1[6 + o]) + x2 * __ldg(&W1[12 + o]);
        float es0 = h[0] * __ldg(&a_src1[0]) + h[1] * __ldg(&a_src1[1]) + h[2] * __ldg(&a_src1[2]);
        float es1 = h[3] * __ldg(&a_src1[3]) + h[4] * __ldg(&a_src1[4]) + h[5] * __ldg(&a_src1[5]);
        float ed0 = h[0] * __ldg(&a_dst1[0]) + h[1] * __ldg(&a_dst1[1]) + h[2] * __ldg(&a_dst1[2]);
        float ed1 = h[3] * __ldg(&a_dst1[3]) + h[4] * __ldg(&a_dst1[4]) + h[5] * __ldg(&a_dst1[5]);
        *(float4*)&g_hes[(size_t)n * 8]     = make_float4(es0, es1, h[0], h[1]);
        *(float4*)&g_hes[(size_t)n * 8 + 4] = make_float4(h[2], h[3], h[4], h[5]);
        g_ed[n * 2 + 0] = ed0;
        g_ed[n * 2 + 1] = ed1;
    } else if (tid < 20) {
        g_hid[blk * 4 + (tid - 16)] = 0.f;         // 2048*4 = 8192 = B*MLP_H
    }

    // -- adj scan: 16 rows, diagonal skipped (self-loop handled implicitly in agg kernels) --
    const int row0 = blockIdx.x * 16;
    const float4* a4 = (const float4*)(adj + (size_t)b * N * N);
    const int col4 = tid & 127;
    const int rhalf = tid >> 7;
    const int jb = col4 * 4;
#pragma unroll
    for (int it = 0; it < 8; it++) {
        int i = row0 + it * 2 + rhalf;
        float4 av = a4[(size_t)i * 128 + col4];
        if (av.x + av.y + av.z + av.w > 0.f) {     // entries are 0/1
            if (av.x > 0.f && i != jb) {
                int p = atomicAdd(&g_cnt[b * N + jb], 1);
                if (p < MAXE) g_src[(size_t)(b * N + jb) * MAXE + p] = (short)i;
            }
            if (av.y > 0.f && i != jb + 1) {
                int p = atomicAdd(&g_cnt[b * N + jb + 1], 1);
                if (p < MAXE) g_src[(size_t)(b * N + jb + 1) * MAXE + p] = (short)i;
            }
            if (av.z > 0.f && i != jb + 2) {
                int p = atomicAdd(&g_cnt[b * N + jb + 2], 1);
                if (p < MAXE) g_src[(size_t)(b * N + jb + 2) * MAXE + p] = (short)i;
            }
            if (av.w > 0.f && i != jb + 3) {
                int p = atomicAdd(&g_cnt[b * N + jb + 3], 1);
                if (p < MAXE) g_src[(size_t)(b * N + jb + 3) * MAXE + p] = (short)i;
            }
        }
    }
}

// ============ agg1: layer-1 aggregation (implicit self-loop) + h2/es2/ed2 epilogue ============
__global__ void __launch_bounds__(256) k_agg1(
        const float* __restrict__ b1, const float* __restrict__ W2,
        const float* __restrict__ a_src2, const float* __restrict__ a_dst2) {
    int gid = blockIdx.x * 256 + threadIdx.x;      // BN*8 threads
    int t = gid >> 3;
    int sl = gid & 7;
    int b = t >> 9;
    float ed0 = g_ed[t * 2 + 0], ed1 = g_ed[t * 2 + 1];
    int cnt = min(g_cnt[t], MAXE);
    const short* lst = &g_src[(size_t)t * MAXE];

    float s0 = 0.f, s1 = 0.f;
    float A00 = 0.f, A01 = 0.f, A02 = 0.f, A10 = 0.f, A11 = 0.f, A12 = 0.f;
    if (sl == 0) {                                 // implicit self-loop, added exactly once
        float4 p0 = *(const float4*)&g_hes[(size_t)t * 8];
        float4 p1 = *(const float4*)&g_hes[(size_t)t * 8 + 4];
        float e0 = __expf(lrelu(p0.x + ed0));
        float e1 = __expf(lrelu(p0.y + ed1));
        s0 = e0; A00 = e0 * p0.z; A01 = e0 * p0.w; A02 = e0 * p1.x;
        s1 = e1; A10 = e1 * p1.y; A11 = e1 * p1.z; A12 = e1 * p1.w;
    }
    for (int e = sl; e < cnt; e += 8) {
        int i = lst[e];
        float4 p0 = *(const float4*)&g_hes[(size_t)(b * N + i) * 8];
        float4 p1 = *(const float4*)&g_hes[(size_t)(b * N + i) * 8 + 4];
        float e0 = __expf(lrelu(p0.x + ed0));
        float e1 = __expf(lrelu(p0.y + ed1));
        s0 += e0; A00 += e0 * p0.z; A01 += e0 * p0.w; A02 += e0 * p1.x;
        s1 += e1; A10 += e1 * p1.y; A11 += e1 * p1.z; A12 += e1 * p1.w;
    }
#pragma unroll
    for (int off = 4; off; off >>= 1) {
        s0  += __shfl_xor_sync(0xffffffffu, s0, off);
        s1  += __shfl_xor_sync(0xffffffffu, s1, off);
        A00 += __shfl_xor_sync(0xffffffffu, A00, off);
        A01 += __shfl_xor_sync(0xffffffffu, A01, off);
        A02 += __shfl_xor_sync(0xffffffffu, A02, off);
        A10 += __shfl_xor_sync(0xffffffffu, A10, off);
        A11 += __shfl_xor_sync(0xffffffffu, A11, off);
        A12 += __shfl_xor_sync(0xffffffffu, A12, off);
    }
    if (sl == 0) {
        float i0 = 1.f / s0, i1 = 1.f / s1;
        float g[6];
        g[0] = relu(A00 * i0 + __ldg(&b1[0]));
        g[1] = relu(A01 * i0 + __ldg(&b1[1]));
        g[2] = relu(A02 * i0 + __ldg(&b1[2]));
        g[3] = relu(A10 * i1 + __ldg(&b1[3]));
        g[4] = relu(A11 * i1 + __ldg(&b1[4]));
        g[5] = relu(A12 * i1 + __ldg(&b1[5]));
        // h2 = g1 @ W2; es2/ed2 — computed ONCE per node (removes 27 FMA/edge from agg2)
        float h0 = 0.f, h1 = 0.f, h2 = 0.f;
#pragma unroll
        for (int f = 0; f < 6; f++) {
            h0 += g[f] * __ldg(&W2[f * 3 + 0]);
            h1 += g[f] * __ldg(&W2[f * 3 + 1]);
            h2 += g[f] * __ldg(&W2[f * 3 + 2]);
        }
        float es2 = h0 * __ldg(&a_src2[0]) + h1 * __ldg(&a_src2[1]) + h2 * __ldg(&a_src2[2]);
        float ed2 = h0 * __ldg(&a_dst2[0]) + h1 * __ldg(&a_dst2[1]) + h2 * __ldg(&a_dst2[2]);
        *(float4*)&g_h2es[(size_t)t * 4] = make_float4(es2, h0, h1, h2);
        g_ed2[t] = ed2;
    }
}

// ============ agg2: layer-2 aggregation, 16B/edge, implicit self-loop ============
__global__ void __launch_bounds__(256) k_agg2(const float* __restrict__ b2) {
    int gid = blockIdx.x * 256 + threadIdx.x;      // BN*8 threads
    int t = gid >> 3;
    int sl = gid & 7;
    int b = t >> 9;
    float edj = g_ed2[t];
    int cnt = min(g_cnt[t], MAXE);
    const short* lst = &g_src[(size_t)t * MAXE];

    float s = 0.f, a0 = 0.f, a1 = 0.f, a2 = 0.f;
    if (sl == 0) {                                 // implicit self-loop
        float4 q = *(const float4*)&g_h2es[(size_t)t * 4];
        float ev = __expf(lrelu(q.x + edj));
        s = ev; a0 = ev * q.y; a1 = ev * q.z; a2 = ev * q.w;
    }
    for (int e = sl; e < cnt; e += 8) {
        int i = lst[e];
        float4 q = *(const float4*)&g_h2es[(size_t)(b * N + i) * 4];
        float ev = __expf(lrelu(q.x + edj));
        s += ev; a0 += ev * q.y; a1 += ev * q.z; a2 += ev * q.w;
    }
#pragma unroll
    for (int off = 4; off; off >>= 1) {
        s  += __shfl_xor_sync(0xffffffffu, s, off);
        a0 += __shfl_xor_sync(0xffffffffu, a0, off);
        a1 += __shfl_xor_sync(0xffffffffu, a1, off);
        a2 += __shfl_xor_sync(0xffffffffu, a2, off);
    }
    if (sl == 0) {
        float inv = 1.f / s;
        g_g2[(size_t)t * 3 + 0] = a0 * inv + __ldg(&b2[0]);
        g_g2[(size_t)t * 3 + 1] = a1 * inv + __ldg(&b2[1]);
        g_g2[(size_t)t * 3 + 2] = a2 * inv + __ldg(&b2[2]);
    }
}

// ============ mlp1: layer-1 GEMM; grid (4 hid x 18 k x 2 batch) = 144 blocks ============
#define KTILE 128
#define KTILES 18
#define HTILE 32
#define BTILE 32
__global__ void __launch_bounds__(256) k_mlp1(
        const float* __restrict__ idx, const float* __restrict__ y,
        const float* __restrict__ Wf1) {
    __shared__ float Wsh[KTILE * HTILE];           // [k][h], 16 KB
    __shared__ float fsh[BTILE * (KTILE + 1)];     // [b][k] pad, 16.5 KB

    const int tid = threadIdx.x;
    const int hid0 = blockIdx.x * HTILE;
    const int k0 = blockIdx.y * KTILE;
    const int b0 = blockIdx.z * BTILE;

#pragma unroll
    for (int i = 0; i < (KTILE * HTILE) / 256; i++) {
        int e = tid + i * 256;
        int k = e >> 5, h = e & 31;
        int kk = k0 + k;
        Wsh[e] = (kk < FC_IN) ? Wf1[kk * MLP_H + hid0 + h] : 0.f;
    }
#pragma unroll
    for (int i = 0; i < (BTILE * KTILE) / 256; i++) {
        int e = tid + i * 256;
        int bb = e >> 7, k = e & 127;
        int kk = k0 + k;
        int b = b0 + bb;
        float v = 0.f;
        if (kk < 512)            v = idx[b * 512 + kk];
        else if (kk < 2048)      v = g_g2[b * 1536 + (kk - 512)];
        else if (kk < FC_IN)     v = y[b * Y_LEN + (kk - 2048)];
        fsh[bb * (KTILE + 1) + k] = v;
    }
    __syncthreads();

    const int bb = tid & 31;
    const int h4 = (tid >> 5) * 4;
    float acc[4] = {};
#pragma unroll 4
    for (int k = 0; k < KTILE; k++) {
        float f = fsh[bb * (KTILE + 1) + k];
        float4 w = *(const float4*)&Wsh[k * HTILE + h4];
        acc[0] += f * w.x; acc[1] += f * w.y; acc[2] += f * w.z; acc[3] += f * w.w;
    }
#pragma unroll
    for (int u = 0; u < 4; u++)
        atomicAdd(&g_hid[(b0 + bb) * MLP_H + hid0 + h4 + u], acc[u]);
}

// ============ mlp2: out = relu(hid+bf1) @ Wf2 + bf2; tail re-zeroes g_cnt for next call ============
__global__ void __launch_bounds__(256) k_mlp2(
        const float* __restrict__ bf1, const float* __restrict__ Wf2,
        const float* __restrict__ bf2, float* __restrict__ out) {
    __shared__ float sh[MLP_H];
    const int b = blockIdx.x >> 1;
    const int o = (blockIdx.x & 1) * 256 + threadIdx.x;
    if (threadIdx.x < MLP_H)
        sh[threadIdx.x] = relu(g_hid[b * MLP_H + threadIdx.x] + __ldg(&bf1[threadIdx.x]));
    __syncthreads();
    float acc = __ldg(&bf2[o]);
#pragma unroll 8
    for (int t = 0; t < MLP_H; t++)
        acc += sh[t] * Wf2[t * N_ACT + o];
    out[b * N_ACT + o] = acc;
    // re-zero edge counters for the next invocation (128 blocks * 256 threads = BN exactly)
    g_cnt[blockIdx.x * 256 + threadIdx.x] = 0;
}

extern "C" void kernel_launch(void* const* d_in, const int* in_sizes, int n_in,
                              void* d_out, int out_size) {
    const float* idx    = (const float*)d_in[0];
    const float* x      = (const float*)d_in[1];
    const float* y      = (const float*)d_in[2];
    const float* adj    = (const float*)d_in[3];
    const float* W1     = (const float*)d_in[4];
    const float* a_src1 = (const float*)d_in[5];
    const float* a_dst1 = (const float*)d_in[6];
    const float* b1     = (const float*)d_in[7];
    const float* W2     = (const float*)d_in[8];
    const float* a_src2 = (const float*)d_in[9];
    const float* a_dst2 = (const float*)d_in[10];
    const float* b2     = (const float*)d_in[11];
    const float* Wf1    = (const float*)d_in[12];
    const float* bf1    = (const float*)d_in[13];
    const float* Wf2    = (const float*)d_in[14];
    const float* bf2    = (const float*)d_in[15];
    float* out = (float*)d_out;

    k_scan<<<dim3(32, B), 256>>>(adj, x, W1, a_src1, a_dst1);
    k_agg1<<<BN * 8 / 256, 256>>>(b1, W2, a_src2, a_dst2);
    k_agg2<<<BN * 8 / 256, 256>>>(b2);
    k_mlp1<<<dim3(MLP_H / HTILE, KTILES, B / BTILE), 256>>>(idx, y, Wf1);
    k_mlp2<<<B * 2, 256>>>(bf1, Wf2, bf2, out);
}